// round 3
// baseline (speedup 1.0000x reference)
#include <cuda_runtime.h>
#include <cuda_bf16.h>
#include <cstdint>

// Problem constants
#define SRC  2048
#define TGT  2048
#define BB   16
#define HH   512
#define HH2  1024

// Tiling
#define MT   64          // t-rows per CTA
#define NS   32          // s-rows per inner iteration
#define QSTR (HH + 4)    // smem row stride for Q/KV (pad 4 -> conflict-friendly)
#define PSTR (NS + 4)    // smem row stride for scores/P

#define NEG_INF (-__int_as_float(0x7f800000))

// Scratch for summed encoder states, laid out [B][S][H], FULL fp32.
__device__ float g_oe[(size_t)BB * SRC * HH];

__device__ __forceinline__ uint32_t f2tf(float x) {
    uint32_t u;
    asm("cvt.rna.tf32.f32 %0, %1;" : "=r"(u) : "f"(x));
    return u;
}

// Split x into hi (tf32) + lo (tf32 of exact residual).
__device__ __forceinline__ void tfsplit(float x, uint32_t& hi, uint32_t& lo) {
    hi = f2tf(x);
    lo = f2tf(x - __uint_as_float(hi));
}

__device__ __forceinline__ void mma8(float* c,
                                     uint32_t a0, uint32_t a1, uint32_t a2, uint32_t a3,
                                     uint32_t b0, uint32_t b1) {
    asm volatile(
        "mma.sync.aligned.m16n8k8.row.col.f32.tf32.tf32.f32 "
        "{%0,%1,%2,%3}, {%4,%5,%6,%7}, {%8,%9}, {%0,%1,%2,%3};"
        : "+f"(c[0]), "+f"(c[1]), "+f"(c[2]), "+f"(c[3])
        : "r"(a0), "r"(a1), "r"(a2), "r"(a3), "r"(b0), "r"(b1));
}

// ---------------------------------------------------------------------------
// Pre-pass: g_oe[b][s][h] = out_e[s][b][h] + out_e[s][b][512+h]   (fp32)
// ---------------------------------------------------------------------------
__global__ void __launch_bounds__(256)
prep_oe_kernel(const float* __restrict__ oe_raw) {
    size_t i = (size_t)blockIdx.x * blockDim.x + threadIdx.x;   // over B*S*H/4
    const size_t total = (size_t)BB * SRC * HH / 4;
    if (i >= total) return;
    size_t c4   = i % (HH / 4);
    size_t rest = i / (HH / 4);
    size_t s = rest % SRC;
    size_t b = rest / SRC;
    const float* p = oe_raw + s * (size_t)(BB * HH2) + b * HH2 + c4 * 4;
    float4 x = *(const float4*)p;
    float4 y = *(const float4*)(p + HH);
    float4 r;
    r.x = x.x + y.x;
    r.y = x.y + y.y;
    r.z = x.z + y.z;
    r.w = x.w + y.w;
    *(float4*)(g_oe + b * (size_t)(SRC * HH) + s * HH + c4 * 4) = r;
}

// ---------------------------------------------------------------------------
// Fused flash attention with compensated-tf32 precision.
//   QK^T: 3xTF32 split (fp32-accurate scores)
//   P.V : V split into hi+lo (fp32-accurate V), P single tf32
// ---------------------------------------------------------------------------
__global__ void __launch_bounds__(256, 1)
flash_kernel(const float* __restrict__ od, float* __restrict__ out) {
    extern __shared__ float sm[];
    float* qs   = sm;                       // MT * QSTR (fp32)
    float* kv   = qs + MT * QSTR;           // NS * QSTR (fp32)
    float* ps   = kv + NS * QSTR;           // MT * PSTR
    float* mrow = ps + MT * PSTR;           // MT
    float* lrow = mrow + MT;                // MT
    float* srow = lrow + MT;                // MT

    const int b   = blockIdx.y;
    const int t0  = blockIdx.x * MT;
    const int tid = threadIdx.x;
    const int lane = tid & 31;
    const int wid  = tid >> 5;
    const int g    = lane >> 2;      // groupID
    const int tig  = lane & 3;       // threadID_in_group
    const int mw   = wid >> 1;
    const int nw   = wid & 1;
    const int m0   = mw * 16;

    // --- load Q tile (fp32) ---
    {
        const float* qg = od + (size_t)t0 * (BB * HH) + (size_t)b * HH;
        for (int idx = tid; idx < MT * (HH / 4); idx += 256) {
            int r = idx >> 7;               // HH/4 = 128
            int c = (idx & 127) << 2;
            float4 v = *(const float4*)(qg + (size_t)r * (BB * HH) + c);
            *(float4*)(&qs[r * QSTR + c]) = v;
        }
    }
    if (tid < MT) { mrow[tid] = NEG_INF; lrow[tid] = 0.f; }

    // O accumulators: 32 n8-fragments x 4 regs. Rows: c0,c1 -> m0+g ; c2,c3 -> m0+g+8
    float o[128];
#pragma unroll
    for (int i = 0; i < 128; ++i) o[i] = 0.f;

    const float* kg = g_oe + (size_t)b * (SRC * HH);

    for (int si = 0; si < SRC / NS; ++si) {
        __syncthreads();
        // --- load KV tile (fp32) ---
        for (int idx = tid; idx < NS * (HH / 4); idx += 256) {
            int r = idx >> 7;
            int c = (idx & 127) << 2;
            float4 v = *(const float4*)(kg + (size_t)(si * NS + r) * HH + c);
            *(float4*)(&kv[r * QSTR + c]) = v;
        }
        __syncthreads();

        // --- S = Q . K^T  (warp tile 16x16, K=512) with 3xTF32 split ---
        float acc[2][4] = {{0.f, 0.f, 0.f, 0.f}, {0.f, 0.f, 0.f, 0.f}};
#pragma unroll 2
        for (int kk = 0; kk < HH / 8; ++kk) {
            const int k0 = kk * 8;
            float qa0 = qs[(m0 + g) * QSTR + k0 + tig];
            float qa1 = qs[(m0 + g + 8) * QSTR + k0 + tig];
            float qa2 = qs[(m0 + g) * QSTR + k0 + tig + 4];
            float qa3 = qs[(m0 + g + 8) * QSTR + k0 + tig + 4];
            uint32_t a0h, a0l, a1h, a1l, a2h, a2l, a3h, a3l;
            tfsplit(qa0, a0h, a0l);
            tfsplit(qa1, a1h, a1l);
            tfsplit(qa2, a2h, a2l);
            tfsplit(qa3, a3h, a3l);
#pragma unroll
            for (int nn = 0; nn < 2; ++nn) {
                const int sb = nw * 16 + nn * 8;      // s-col base
                float kb0 = kv[(sb + g) * QSTR + k0 + tig];
                float kb1 = kv[(sb + g) * QSTR + k0 + tig + 4];
                uint32_t b0h, b0l, b1h, b1l;
                tfsplit(kb0, b0h, b0l);
                tfsplit(kb1, b1h, b1l);
                mma8(acc[nn], a0h, a1h, a2h, a3h, b0h, b1h);
                mma8(acc[nn], a0h, a1h, a2h, a3h, b0l, b1l);
                mma8(acc[nn], a0l, a1l, a2l, a3l, b0h, b1h);
            }
        }
        // write scores to smem
#pragma unroll
        for (int nn = 0; nn < 2; ++nn) {
            const int cb = nw * 16 + nn * 8 + 2 * tig;
            ps[(m0 + g) * PSTR + cb]         = acc[nn][0];
            ps[(m0 + g) * PSTR + cb + 1]     = acc[nn][1];
            ps[(m0 + g + 8) * PSTR + cb]     = acc[nn][2];
            ps[(m0 + g + 8) * PSTR + cb + 1] = acc[nn][3];
        }
        __syncthreads();

        // --- online softmax over this 32-col tile: 4 threads per row ---
        {
            const int r = tid >> 2;
            const int q = tid & 3;
            float* pr = ps + r * PSTR + q * 8;
            float mx = pr[0];
#pragma unroll
            for (int j = 1; j < 8; ++j) mx = fmaxf(mx, pr[j]);
            mx = fmaxf(mx, __shfl_xor_sync(0xffffffffu, mx, 1));
            mx = fmaxf(mx, __shfl_xor_sync(0xffffffffu, mx, 2));
            const float mo = mrow[r];
            const float mn = fmaxf(mo, mx);
            const float sc = __expf(mo - mn);
            float sum = 0.f;
#pragma unroll
            for (int j = 0; j < 8; ++j) {
                float p = __expf(pr[j] - mn);
                sum += p;
                pr[j] = __uint_as_float(f2tf(p));
            }
            sum += __shfl_xor_sync(0xffffffffu, sum, 1);
            sum += __shfl_xor_sync(0xffffffffu, sum, 2);
            if (q == 0) {
                mrow[r] = mn;
                lrow[r] = lrow[r] * sc + sum;
                srow[r] = sc;
            }
        }
        __syncthreads();

        // --- rescale O by per-row correction ---
        {
            const float s0 = srow[m0 + g];
            const float s1 = srow[m0 + g + 8];
#pragma unroll
            for (int nf = 0; nf < 32; ++nf) {
                o[4 * nf + 0] *= s0;
                o[4 * nf + 1] *= s0;
                o[4 * nf + 2] *= s1;
                o[4 * nf + 3] *= s1;
            }
        }

        // --- O += P . V   (M=64, N=512, K=32), V split hi+lo ---
#pragma unroll
        for (int kk = 0; kk < NS / 8; ++kk) {
            const int k0 = kk * 8;
            uint32_t a0 = __float_as_uint(ps[(m0 + g) * PSTR + k0 + tig]);
            uint32_t a1 = __float_as_uint(ps[(m0 + g + 8) * PSTR + k0 + tig]);
            uint32_t a2 = __float_as_uint(ps[(m0 + g) * PSTR + k0 + tig + 4]);
            uint32_t a3 = __float_as_uint(ps[(m0 + g + 8) * PSTR + k0 + tig + 4]);
#pragma unroll
            for (int nf = 0; nf < 32; ++nf) {
                const int h0 = nw * 256 + nf * 8;
                float v0 = kv[(k0 + tig) * QSTR + h0 + g];
                float v1 = kv[(k0 + tig + 4) * QSTR + h0 + g];
                uint32_t b0h, b0l, b1h, b1l;
                tfsplit(v0, b0h, b0l);
                tfsplit(v1, b1h, b1l);
                mma8(&o[4 * nf], a0, a1, a2, a3, b0h, b1h);
                mma8(&o[4 * nf], a0, a1, a2, a3, b0l, b1l);
            }
        }
    }

    // --- epilogue: divide by l, store [T,B,H] fp32 ---
    const float inv0 = 1.f / lrow[m0 + g];
    const float inv1 = 1.f / lrow[m0 + g + 8];
    float* o0 = out + (size_t)(t0 + m0 + g) * (BB * HH) + (size_t)b * HH;
    float* o1 = out + (size_t)(t0 + m0 + g + 8) * (BB * HH) + (size_t)b * HH;
#pragma unroll
    for (int nf = 0; nf < 32; ++nf) {
        const int col = nw * 256 + nf * 8 + 2 * tig;
        float2 v0 = make_float2(o[4 * nf + 0] * inv0, o[4 * nf + 1] * inv0);
        float2 v1 = make_float2(o[4 * nf + 2] * inv1, o[4 * nf + 3] * inv1);
        *(float2*)(o0 + col) = v0;
        *(float2*)(o1 + col) = v1;
    }
}

// ---------------------------------------------------------------------------
extern "C" void kernel_launch(void* const* d_in, const int* in_sizes, int n_in,
                              void* d_out, int out_size) {
    // Identify inputs by element count (robust to ordering):
    //   out_e: S*B*2H = 33554432, out_d: T*B*H = 16777216, in_e: S*B = 32768 (unused)
    const float* oe_raw = nullptr;
    const float* od = nullptr;
    for (int i = 0; i < n_in; ++i) {
        if (in_sizes[i] == SRC * BB * HH2) oe_raw = (const float*)d_in[i];
        else if (in_sizes[i] == TGT * BB * HH) od = (const float*)d_in[i];
    }
    float* out = (float*)d_out;

    const size_t smem_bytes =
        (size_t)(MT * QSTR + NS * QSTR + MT * PSTR + 3 * MT) * sizeof(float); // ~208 KB
    cudaFuncSetAttribute(flash_kernel, cudaFuncAttributeMaxDynamicSharedMemorySize,
                         (int)smem_bytes);

    {
        const size_t total = (size_t)BB * SRC * HH / 4;
        const int threads = 256;
        const int blocks = (int)((total + threads - 1) / threads);
        prep_oe_kernel<<<blocks, threads>>>(oe_raw);
    }
    {
        dim3 grid(TGT / MT, BB);
        flash_kernel<<<grid, 256, smem_bytes>>>(od, out);
    }
}

// round 4
// speedup vs baseline: 2.4621x; 2.4621x over previous
#include <cuda_runtime.h>
#include <cuda_fp16.h>
#include <cstdint>

// Problem constants
#define SRC  2048
#define TGT  2048
#define BB   16
#define HH   512
#define HH2  1024

// Tiling
#define MT   64          // t-rows per CTA
#define NS   32          // s-rows per inner iteration
#define HSTR 520         // half-row stride (512 + 8) -> ldmatrix conflict-free
#define PSTR 36          // fp32 score row stride
#define PSTRH 40         // fp16 P row stride (80B, 16B-aligned, conflict-free)

#define NEG_INF (-__int_as_float(0x7f800000))

// Pre-split summed encoder states [B][S][H], fp16 hi + fp16 lo planes.
__device__ __half g_hi[(size_t)BB * SRC * HH];
__device__ __half g_lo[(size_t)BB * SRC * HH];

__device__ __forceinline__ uint32_t s2u(const void* p) {
    return (uint32_t)__cvta_generic_to_shared(p);
}

__device__ __forceinline__ void ldm_x4(uint32_t& r0, uint32_t& r1, uint32_t& r2, uint32_t& r3,
                                       uint32_t addr) {
    asm volatile("ldmatrix.sync.aligned.m8n8.x4.shared.b16 {%0,%1,%2,%3}, [%4];"
                 : "=r"(r0), "=r"(r1), "=r"(r2), "=r"(r3) : "r"(addr));
}

__device__ __forceinline__ void ldm_x2t(uint32_t& r0, uint32_t& r1, uint32_t addr) {
    asm volatile("ldmatrix.sync.aligned.m8n8.x2.trans.shared.b16 {%0,%1}, [%2];"
                 : "=r"(r0), "=r"(r1) : "r"(addr));
}

__device__ __forceinline__ void mma16(float* c,
                                      uint32_t a0, uint32_t a1, uint32_t a2, uint32_t a3,
                                      uint32_t b0, uint32_t b1) {
    asm volatile(
        "mma.sync.aligned.m16n8k16.row.col.f32.f16.f16.f32 "
        "{%0,%1,%2,%3}, {%4,%5,%6,%7}, {%8,%9}, {%0,%1,%2,%3};"
        : "+f"(c[0]), "+f"(c[1]), "+f"(c[2]), "+f"(c[3])
        : "r"(a0), "r"(a1), "r"(a2), "r"(a3), "r"(b0), "r"(b1));
}

// ---------------------------------------------------------------------------
// Pre-pass: sum bidirectional halves, split into fp16 hi/lo planes.
// ---------------------------------------------------------------------------
__global__ void __launch_bounds__(256)
prep_oe_kernel(const float* __restrict__ oe_raw) {
    size_t i = (size_t)blockIdx.x * blockDim.x + threadIdx.x;   // over B*S*H/4
    const size_t total = (size_t)BB * SRC * HH / 4;
    if (i >= total) return;
    size_t c4   = i % (HH / 4);
    size_t rest = i / (HH / 4);
    size_t s = rest % SRC;
    size_t b = rest / SRC;
    const float* p = oe_raw + s * (size_t)(BB * HH2) + b * HH2 + c4 * 4;
    float4 x = *(const float4*)p;
    float4 y = *(const float4*)(p + HH);
    float v[4] = {x.x + y.x, x.y + y.y, x.z + y.z, x.w + y.w};
    __half h[4], l[4];
#pragma unroll
    for (int j = 0; j < 4; ++j) {
        h[j] = __float2half_rn(v[j]);
        l[j] = __float2half_rn(v[j] - __half2float(h[j]));
    }
    size_t o = b * (size_t)(SRC * HH) + s * HH + c4 * 4;
    *(__half2*)(g_hi + o)     = __halves2half2(h[0], h[1]);
    *(__half2*)(g_hi + o + 2) = __halves2half2(h[2], h[3]);
    *(__half2*)(g_lo + o)     = __halves2half2(l[0], l[1]);
    *(__half2*)(g_lo + o + 2) = __halves2half2(l[2], l[3]);
}

// ---------------------------------------------------------------------------
// Fused flash attention, fp16-split compensated precision.
//   QK^T: qh*kh + qh*kl + ql*kh  (fp32-accurate scores)
//   P.V : p*(vh) + p*(vl)        (fp32-accurate V, P fp16)
// ---------------------------------------------------------------------------
__global__ void __launch_bounds__(256, 1)
flash_kernel(const float* __restrict__ od, float* __restrict__ out) {
    extern __shared__ char smraw[];
    __half* q_hi  = (__half*)smraw;                 // 64*520 halves
    __half* q_lo  = q_hi + MT * HSTR;
    __half* kv_hi = q_lo + MT * HSTR;               // 32*520
    __half* kv_lo = kv_hi + NS * HSTR;
    float*  ps    = (float*)(kv_lo + NS * HSTR);    // 64*36 fp32 scores
    __half* ps_h  = (__half*)(ps + MT * PSTR);      // 64*40 fp16 P
    float*  mrow  = (float*)(ps_h + MT * PSTRH);
    float*  lrow  = mrow + MT;
    float*  srow  = lrow + MT;

    const int b    = blockIdx.y;
    const int t0   = blockIdx.x * MT;
    const int tid  = threadIdx.x;
    const int lane = tid & 31;
    const int wid  = tid >> 5;
    const int g    = lane >> 2;
    const int tig  = lane & 3;
    const int mw   = wid >> 1;
    const int nw   = wid & 1;
    const int m0   = mw * 16;

    // --- load + split Q tile ---
    {
        const float* qg = od + (size_t)t0 * (BB * HH) + (size_t)b * HH;
        for (int idx = tid; idx < MT * (HH / 4); idx += 256) {
            int r = idx >> 7;               // HH/4 = 128 per row
            int c = (idx & 127) << 2;
            float4 v = *(const float4*)(qg + (size_t)r * (BB * HH) + c);
            float vv[4] = {v.x, v.y, v.z, v.w};
            __half h[4], l[4];
#pragma unroll
            for (int j = 0; j < 4; ++j) {
                h[j] = __float2half_rn(vv[j]);
                l[j] = __float2half_rn(vv[j] - __half2float(h[j]));
            }
            int o = r * HSTR + c;
            *(__half2*)(q_hi + o)     = __halves2half2(h[0], h[1]);
            *(__half2*)(q_hi + o + 2) = __halves2half2(h[2], h[3]);
            *(__half2*)(q_lo + o)     = __halves2half2(l[0], l[1]);
            *(__half2*)(q_lo + o + 2) = __halves2half2(l[2], l[3]);
        }
    }
    if (tid < MT) { mrow[tid] = NEG_INF; lrow[tid] = 0.f; }

    float o[128];
#pragma unroll
    for (int i = 0; i < 128; ++i) o[i] = 0.f;

    // ldmatrix base addresses (bytes, smem space)
    // A pattern (Q and P): row = base + ((lane>>3)&1)*8 + (lane&7), col = (lane>>4)*8
    const int a_row = m0 + ((lane >> 3) & 1) * 8 + (lane & 7);
    const int a_col = (lane >> 4) * 8;
    const uint32_t qa_hi = s2u(q_hi) + (uint32_t)(a_row * HSTR + a_col) * 2;
    const uint32_t qa_lo = s2u(q_lo) + (uint32_t)(a_row * HSTR + a_col) * 2;
    const uint32_t pa    = s2u(ps_h) + (uint32_t)(a_row * PSTRH + a_col) * 2;
    // B pattern for K: s = nw*16 + ((lane>>4)&1)*8 + (lane&7), kcol = ((lane>>3)&1)*8
    const int kb_row = nw * 16 + ((lane >> 4) & 1) * 8 + (lane & 7);
    const int kb_col = ((lane >> 3) & 1) * 8;
    const uint32_t kb_hi = s2u(kv_hi) + (uint32_t)(kb_row * HSTR + kb_col) * 2;
    const uint32_t kb_lo = s2u(kv_lo) + (uint32_t)(kb_row * HSTR + kb_col) * 2;
    // V trans pattern: row = (lane&15) within 16-row k-chunk
    const uint32_t vb_hi = s2u(kv_hi) + (uint32_t)((lane & 15) * HSTR) * 2;
    const uint32_t vb_lo = s2u(kv_lo) + (uint32_t)((lane & 15) * HSTR) * 2;

    const size_t kvoff = (size_t)b * (SRC * HH);

    for (int si = 0; si < SRC / NS; ++si) {
        __syncthreads();
        // --- load KV hi/lo tiles (already split) ---
        {
            const __half* gh = g_hi + kvoff + (size_t)si * NS * HH;
            const __half* gl = g_lo + kvoff + (size_t)si * NS * HH;
            for (int u = tid; u < NS * HH / 8; u += 256) {   // 2048 int4 units
                int r = u >> 6;                 // 64 units per row
                int c = (u & 63) << 3;
                *(int4*)(kv_hi + r * HSTR + c) = *(const int4*)(gh + r * HH + c);
                *(int4*)(kv_lo + r * HSTR + c) = *(const int4*)(gl + r * HH + c);
            }
        }
        __syncthreads();

        // --- S = Q.K^T (warp tile 16x16, K=512, 3-term fp16 split) ---
        float acc[2][4] = {{0.f,0.f,0.f,0.f},{0.f,0.f,0.f,0.f}};
#pragma unroll 2
        for (int kk = 0; kk < HH / 16; ++kk) {
            const uint32_t off = kk * 32;       // 16 halves = 32 bytes
            uint32_t ah0, ah1, ah2, ah3, al0, al1, al2, al3;
            ldm_x4(ah0, ah1, ah2, ah3, qa_hi + off);
            ldm_x4(al0, al1, al2, al3, qa_lo + off);
            uint32_t kh0, kh1, kh2, kh3, kl0, kl1, kl2, kl3;
            ldm_x4(kh0, kh1, kh2, kh3, kb_hi + off);
            ldm_x4(kl0, kl1, kl2, kl3, kb_lo + off);
            mma16(acc[0], ah0, ah1, ah2, ah3, kh0, kh1);
            mma16(acc[0], ah0, ah1, ah2, ah3, kl0, kl1);
            mma16(acc[0], al0, al1, al2, al3, kh0, kh1);
            mma16(acc[1], ah0, ah1, ah2, ah3, kh2, kh3);
            mma16(acc[1], ah0, ah1, ah2, ah3, kl2, kl3);
            mma16(acc[1], al0, al1, al2, al3, kh2, kh3);
        }
        // write scores (fp32) to smem
#pragma unroll
        for (int nn = 0; nn < 2; ++nn) {
            const int cb = nw * 16 + nn * 8 + 2 * tig;
            ps[(m0 + g) * PSTR + cb]         = acc[nn][0];
            ps[(m0 + g) * PSTR + cb + 1]     = acc[nn][1];
            ps[(m0 + g + 8) * PSTR + cb]     = acc[nn][2];
            ps[(m0 + g + 8) * PSTR + cb + 1] = acc[nn][3];
        }
        __syncthreads();

        // --- online softmax (4 threads per row), write P as fp16 ---
        {
            const int r = tid >> 2;
            const int q = tid & 3;
            const float* pr = ps + r * PSTR + q * 8;
            __half* prh = ps_h + r * PSTRH + q * 8;
            float mx = pr[0];
#pragma unroll
            for (int j = 1; j < 8; ++j) mx = fmaxf(mx, pr[j]);
            mx = fmaxf(mx, __shfl_xor_sync(0xffffffffu, mx, 1));
            mx = fmaxf(mx, __shfl_xor_sync(0xffffffffu, mx, 2));
            const float mo = mrow[r];
            const float mn = fmaxf(mo, mx);
            const float sc = __expf(mo - mn);
            float p[8];
            float sum = 0.f;
#pragma unroll
            for (int j = 0; j < 8; ++j) { p[j] = __expf(pr[j] - mn); sum += p[j]; }
#pragma unroll
            for (int j = 0; j < 8; j += 2)
                *(__half2*)(prh + j) = __halves2half2(__float2half_rn(p[j]),
                                                      __float2half_rn(p[j + 1]));
            sum += __shfl_xor_sync(0xffffffffu, sum, 1);
            sum += __shfl_xor_sync(0xffffffffu, sum, 2);
            if (q == 0) {
                mrow[r] = mn;
                lrow[r] = lrow[r] * sc + sum;
                srow[r] = sc;
            }
        }
        __syncthreads();

        // --- rescale O (skip when no max update) ---
        {
            const float s0 = srow[m0 + g];
            const float s1 = srow[m0 + g + 8];
            if (s0 != 1.f || s1 != 1.f) {
#pragma unroll
                for (int nf = 0; nf < 32; ++nf) {
                    o[4 * nf + 0] *= s0;
                    o[4 * nf + 1] *= s0;
                    o[4 * nf + 2] *= s1;
                    o[4 * nf + 3] *= s1;
                }
            }
        }

        // --- O += P.V (M=64, N=512, K=32; V via ldmatrix.trans, hi+lo) ---
#pragma unroll
        for (int kk = 0; kk < NS / 16; ++kk) {
            uint32_t p0, p1, p2, p3;
            ldm_x4(p0, p1, p2, p3, pa + kk * 32);
            const uint32_t vbh = vb_hi + kk * 16 * HSTR * 2;
            const uint32_t vbl = vb_lo + kk * 16 * HSTR * 2;
#pragma unroll
            for (int nf = 0; nf < 32; ++nf) {
                const uint32_t hb = (uint32_t)(nw * 256 + nf * 8) * 2;
                uint32_t v0, v1, w0, w1;
                ldm_x2t(v0, v1, vbh + hb);
                ldm_x2t(w0, w1, vbl + hb);
                mma16(&o[4 * nf], p0, p1, p2, p3, v0, v1);
                mma16(&o[4 * nf], p0, p1, p2, p3, w0, w1);
            }
        }
    }

    // --- epilogue ---
    const float inv0 = 1.f / lrow[m0 + g];
    const float inv1 = 1.f / lrow[m0 + g + 8];
    float* o0 = out + (size_t)(t0 + m0 + g) * (BB * HH) + (size_t)b * HH;
    float* o1 = out + (size_t)(t0 + m0 + g + 8) * (BB * HH) + (size_t)b * HH;
#pragma unroll
    for (int nf = 0; nf < 32; ++nf) {
        const int col = nw * 256 + nf * 8 + 2 * tig;
        float2 v0 = make_float2(o[4 * nf + 0] * inv0, o[4 * nf + 1] * inv0);
        float2 v1 = make_float2(o[4 * nf + 2] * inv1, o[4 * nf + 3] * inv1);
        *(float2*)(o0 + col) = v0;
        *(float2*)(o1 + col) = v1;
    }
}

// ---------------------------------------------------------------------------
extern "C" void kernel_launch(void* const* d_in, const int* in_sizes, int n_in,
                              void* d_out, int out_size) {
    const float* oe_raw = nullptr;
    const float* od = nullptr;
    for (int i = 0; i < n_in; ++i) {
        if (in_sizes[i] == SRC * BB * HH2) oe_raw = (const float*)d_in[i];
        else if (in_sizes[i] == TGT * BB * HH) od = (const float*)d_in[i];
    }
    float* out = (float*)d_out;

    const size_t smem_bytes =
        (size_t)(MT * HSTR * 2 + NS * HSTR * 2) * sizeof(__half)   // q hi/lo + kv hi/lo
        + (size_t)MT * PSTR * sizeof(float)                        // ps
        + (size_t)MT * PSTRH * sizeof(__half)                      // ps_h
        + 3 * MT * sizeof(float);                                  // mrow/lrow/srow
    cudaFuncSetAttribute(flash_kernel, cudaFuncAttributeMaxDynamicSharedMemorySize,
                         (int)smem_bytes);

    {
        const size_t total = (size_t)BB * SRC * HH / 4;
        const int threads = 256;
        const int blocks = (int)((total + threads - 1) / threads);
        prep_oe_kernel<<<blocks, threads>>>(oe_raw);
    }
    {
        dim3 grid(TGT / MT, BB);
        flash_kernel<<<grid, 256, smem_bytes>>>(od, out);
    }
}

// round 5
// speedup vs baseline: 2.8987x; 1.1773x over previous
#include <cuda_runtime.h>
#include <cuda_fp16.h>
#include <cstdint>

// Problem constants
#define SRC  2048
#define TGT  2048
#define BB   16
#define HH   512
#define HH2  1024

// Tiling
#define MT   64          // t-rows per CTA
#define NS   32          // s-rows per inner iteration
#define HSTR 520         // half-row stride (512 + 8) -> ldmatrix conflict-free
#define PSTR 36          // fp32 score row stride
#define PSTRH 40         // fp16 P row stride (80B, 16B-aligned, conflict-free)

#define NEG_INF (-__int_as_float(0x7f800000))

// Pre-split summed encoder states [B][S][H], fp16 hi + fp16 lo planes.
__device__ __half g_hi[(size_t)BB * SRC * HH];
__device__ __half g_lo[(size_t)BB * SRC * HH];

__device__ __forceinline__ uint32_t s2u(const void* p) {
    return (uint32_t)__cvta_generic_to_shared(p);
}

__device__ __forceinline__ void cp16(uint32_t s, const void* g) {
    asm volatile("cp.async.cg.shared.global [%0], [%1], 16;" :: "r"(s), "l"(g));
}

__device__ __forceinline__ void ldm_x4(uint32_t& r0, uint32_t& r1, uint32_t& r2, uint32_t& r3,
                                       uint32_t addr) {
    asm volatile("ldmatrix.sync.aligned.m8n8.x4.shared.b16 {%0,%1,%2,%3}, [%4];"
                 : "=r"(r0), "=r"(r1), "=r"(r2), "=r"(r3) : "r"(addr));
}

__device__ __forceinline__ void ldm_x4t(uint32_t& r0, uint32_t& r1, uint32_t& r2, uint32_t& r3,
                                        uint32_t addr) {
    asm volatile("ldmatrix.sync.aligned.m8n8.x4.trans.shared.b16 {%0,%1,%2,%3}, [%4];"
                 : "=r"(r0), "=r"(r1), "=r"(r2), "=r"(r3) : "r"(addr));
}

__device__ __forceinline__ void mma16(float* c,
                                      uint32_t a0, uint32_t a1, uint32_t a2, uint32_t a3,
                                      uint32_t b0, uint32_t b1) {
    asm volatile(
        "mma.sync.aligned.m16n8k16.row.col.f32.f16.f16.f32 "
        "{%0,%1,%2,%3}, {%4,%5,%6,%7}, {%8,%9}, {%0,%1,%2,%3};"
        : "+f"(c[0]), "+f"(c[1]), "+f"(c[2]), "+f"(c[3])
        : "r"(a0), "r"(a1), "r"(a2), "r"(a3), "r"(b0), "r"(b1));
}

// ---------------------------------------------------------------------------
// Pre-pass: sum bidirectional halves, split into fp16 hi/lo planes.
// ---------------------------------------------------------------------------
__global__ void __launch_bounds__(256)
prep_oe_kernel(const float* __restrict__ oe_raw) {
    size_t i = (size_t)blockIdx.x * blockDim.x + threadIdx.x;   // over B*S*H/4
    const size_t total = (size_t)BB * SRC * HH / 4;
    if (i >= total) return;
    size_t c4   = i % (HH / 4);
    size_t rest = i / (HH / 4);
    size_t s = rest % SRC;
    size_t b = rest / SRC;
    const float* p = oe_raw + s * (size_t)(BB * HH2) + b * HH2 + c4 * 4;
    float4 x = *(const float4*)p;
    float4 y = *(const float4*)(p + HH);
    float v[4] = {x.x + y.x, x.y + y.y, x.z + y.z, x.w + y.w};
    __half h[4], l[4];
#pragma unroll
    for (int j = 0; j < 4; ++j) {
        h[j] = __float2half_rn(v[j]);
        l[j] = __float2half_rn(v[j] - __half2float(h[j]));
    }
    size_t o = b * (size_t)(SRC * HH) + s * HH + c4 * 4;
    *(__half2*)(g_hi + o)     = __halves2half2(h[0], h[1]);
    *(__half2*)(g_hi + o + 2) = __halves2half2(h[2], h[3]);
    *(__half2*)(g_lo + o)     = __halves2half2(l[0], l[1]);
    *(__half2*)(g_lo + o + 2) = __halves2half2(l[2], l[3]);
}

// ---------------------------------------------------------------------------
// Fused flash attention, fp16-split compensated precision.
//   QK^T: qh*kh + qh*kl + ql*kh  (fp32-accurate scores)
//   P.V : p*vh                   (V fp16; adds ~1.6e-4 rel, within budget)
// ---------------------------------------------------------------------------
__global__ void __launch_bounds__(256, 1)
flash_kernel(const float* __restrict__ od, float* __restrict__ out) {
    extern __shared__ char smraw[];
    __half* q_hi  = (__half*)smraw;                 // 64*520 halves
    __half* q_lo  = q_hi + MT * HSTR;
    __half* kv_hi = q_lo + MT * HSTR;               // 32*520
    __half* kv_lo = kv_hi + NS * HSTR;
    float*  ps    = (float*)(kv_lo + NS * HSTR);    // 64*36 fp32 scores
    __half* ps_h  = (__half*)(ps + MT * PSTR);      // 64*40 fp16 P
    float*  mrow  = (float*)(ps_h + MT * PSTRH);
    float*  lrow  = mrow + MT;
    float*  srow  = lrow + MT;

    const int b    = blockIdx.y;
    const int t0   = blockIdx.x * MT;
    const int tid  = threadIdx.x;
    const int lane = tid & 31;
    const int wid  = tid >> 5;
    const int g    = lane >> 2;
    const int tig  = lane & 3;
    const int mw   = wid >> 1;
    const int nw   = wid & 1;
    const int m0   = mw * 16;

    // --- load + split Q tile ---
    {
        const float* qg = od + (size_t)t0 * (BB * HH) + (size_t)b * HH;
        for (int idx = tid; idx < MT * (HH / 4); idx += 256) {
            int r = idx >> 7;               // HH/4 = 128 per row
            int c = (idx & 127) << 2;
            float4 v = *(const float4*)(qg + (size_t)r * (BB * HH) + c);
            float vv[4] = {v.x, v.y, v.z, v.w};
            __half h[4], l[4];
#pragma unroll
            for (int j = 0; j < 4; ++j) {
                h[j] = __float2half_rn(vv[j]);
                l[j] = __float2half_rn(vv[j] - __half2float(h[j]));
            }
            int o = r * HSTR + c;
            *(__half2*)(q_hi + o)     = __halves2half2(h[0], h[1]);
            *(__half2*)(q_hi + o + 2) = __halves2half2(h[2], h[3]);
            *(__half2*)(q_lo + o)     = __halves2half2(l[0], l[1]);
            *(__half2*)(q_lo + o + 2) = __halves2half2(l[2], l[3]);
        }
    }
    if (tid < MT) { mrow[tid] = NEG_INF; lrow[tid] = 0.f; }

    float o[128];
#pragma unroll
    for (int i = 0; i < 128; ++i) o[i] = 0.f;

    // ldmatrix base addresses (bytes, smem space)
    const int a_row = m0 + ((lane >> 3) & 1) * 8 + (lane & 7);
    const int a_col = (lane >> 4) * 8;
    const uint32_t qa_hi = s2u(q_hi) + (uint32_t)(a_row * HSTR + a_col) * 2;
    const uint32_t qa_lo = s2u(q_lo) + (uint32_t)(a_row * HSTR + a_col) * 2;
    const uint32_t pa    = s2u(ps_h) + (uint32_t)(a_row * PSTRH + a_col) * 2;
    const int kb_row = nw * 16 + ((lane >> 4) & 1) * 8 + (lane & 7);
    const int kb_col = ((lane >> 3) & 1) * 8;
    const uint32_t kb_hi = s2u(kv_hi) + (uint32_t)(kb_row * HSTR + kb_col) * 2;
    const uint32_t kb_lo = s2u(kv_lo) + (uint32_t)(kb_row * HSTR + kb_col) * 2;
    // V x4-trans pattern: lanes 0-15 give k-rows 0..15, lanes 16-31 shift +8 h-cols
    const uint32_t vb_hi = s2u(kv_hi) +
        (uint32_t)((lane & 15) * HSTR + (lane >> 4) * 8) * 2;

    const size_t kvoff = (size_t)b * (SRC * HH);

    for (int si = 0; si < SRC / NS; ++si) {
        __syncthreads();
        // --- async load KV hi/lo tiles ---
        {
            const __half* gh = g_hi + kvoff + (size_t)si * NS * HH;
            const __half* gl = g_lo + kvoff + (size_t)si * NS * HH;
            for (int u = tid; u < NS * HH / 8; u += 256) {   // 2048 int4 units
                int r = u >> 6;                 // 64 units per row
                int c = (u & 63) << 3;
                cp16(s2u(kv_hi + r * HSTR + c), gh + r * HH + c);
                cp16(s2u(kv_lo + r * HSTR + c), gl + r * HH + c);
            }
            asm volatile("cp.async.commit_group;");
            asm volatile("cp.async.wait_group 0;");
        }
        __syncthreads();

        // --- S = Q.K^T (warp tile 16x16, K=512, 3-term fp16 split) ---
        float acc[2][4] = {{0.f,0.f,0.f,0.f},{0.f,0.f,0.f,0.f}};
#pragma unroll 2
        for (int kk = 0; kk < HH / 16; ++kk) {
            const uint32_t off = kk * 32;       // 16 halves = 32 bytes
            uint32_t ah0, ah1, ah2, ah3, al0, al1, al2, al3;
            ldm_x4(ah0, ah1, ah2, ah3, qa_hi + off);
            ldm_x4(al0, al1, al2, al3, qa_lo + off);
            uint32_t kh0, kh1, kh2, kh3, kl0, kl1, kl2, kl3;
            ldm_x4(kh0, kh1, kh2, kh3, kb_hi + off);
            ldm_x4(kl0, kl1, kl2, kl3, kb_lo + off);
            mma16(acc[0], ah0, ah1, ah2, ah3, kh0, kh1);
            mma16(acc[0], ah0, ah1, ah2, ah3, kl0, kl1);
            mma16(acc[0], al0, al1, al2, al3, kh0, kh1);
            mma16(acc[1], ah0, ah1, ah2, ah3, kh2, kh3);
            mma16(acc[1], ah0, ah1, ah2, ah3, kl2, kl3);
            mma16(acc[1], al0, al1, al2, al3, kh2, kh3);
        }
        // write scores (fp32) to smem
#pragma unroll
        for (int nn = 0; nn < 2; ++nn) {
            const int cb = nw * 16 + nn * 8 + 2 * tig;
            ps[(m0 + g) * PSTR + cb]         = acc[nn][0];
            ps[(m0 + g) * PSTR + cb + 1]     = acc[nn][1];
            ps[(m0 + g + 8) * PSTR + cb]     = acc[nn][2];
            ps[(m0 + g + 8) * PSTR + cb + 1] = acc[nn][3];
        }
        __syncthreads();

        // --- online softmax (4 threads per row), write P as fp16 ---
        {
            const int r = tid >> 2;
            const int q = tid & 3;
            const float* pr = ps + r * PSTR + q * 8;
            __half* prh = ps_h + r * PSTRH + q * 8;
            float mx = pr[0];
#pragma unroll
            for (int j = 1; j < 8; ++j) mx = fmaxf(mx, pr[j]);
            mx = fmaxf(mx, __shfl_xor_sync(0xffffffffu, mx, 1));
            mx = fmaxf(mx, __shfl_xor_sync(0xffffffffu, mx, 2));
            const float mo = mrow[r];
            const float mn = fmaxf(mo, mx);
            const float sc = __expf(mo - mn);
            float p[8];
            float sum = 0.f;
#pragma unroll
            for (int j = 0; j < 8; ++j) { p[j] = __expf(pr[j] - mn); sum += p[j]; }
#pragma unroll
            for (int j = 0; j < 8; j += 2)
                *(__half2*)(prh + j) = __halves2half2(__float2half_rn(p[j]),
                                                      __float2half_rn(p[j + 1]));
            sum += __shfl_xor_sync(0xffffffffu, sum, 1);
            sum += __shfl_xor_sync(0xffffffffu, sum, 2);
            if (q == 0) {
                mrow[r] = mn;
                lrow[r] = lrow[r] * sc + sum;
                srow[r] = sc;
            }
        }
        __syncthreads();

        // --- rescale O (skip when no max update) ---
        {
            const float s0 = srow[m0 + g];
            const float s1 = srow[m0 + g + 8];
            if (s0 != 1.f || s1 != 1.f) {
#pragma unroll
                for (int nf = 0; nf < 32; ++nf) {
                    o[4 * nf + 0] *= s0;
                    o[4 * nf + 1] *= s0;
                    o[4 * nf + 2] *= s1;
                    o[4 * nf + 3] *= s1;
                }
            }
        }

        // --- O += P.V (M=64, N=512, K=32; V-hi only via ldmatrix.x4.trans) ---
#pragma unroll
        for (int kk = 0; kk < NS / 16; ++kk) {
            uint32_t p0, p1, p2, p3;
            ldm_x4(p0, p1, p2, p3, pa + kk * 32);
            const uint32_t vbh = vb_hi + kk * 16 * HSTR * 2;
#pragma unroll
            for (int nf = 0; nf < 32; nf += 2) {
                const uint32_t hb = (uint32_t)(nw * 256 + nf * 8) * 2;
                uint32_t v0, v1, v2, v3;
                ldm_x4t(v0, v1, v2, v3, vbh + hb);
                mma16(&o[4 * nf],     p0, p1, p2, p3, v0, v1);
                mma16(&o[4 * (nf+1)], p0, p1, p2, p3, v2, v3);
            }
        }
    }

    // --- epilogue ---
    const float inv0 = 1.f / lrow[m0 + g];
    const float inv1 = 1.f / lrow[m0 + g + 8];
    float* o0 = out + (size_t)(t0 + m0 + g) * (BB * HH) + (size_t)b * HH;
    float* o1 = out + (size_t)(t0 + m0 + g + 8) * (BB * HH) + (size_t)b * HH;
#pragma unroll
    for (int nf = 0; nf < 32; ++nf) {
        const int col = nw * 256 + nf * 8 + 2 * tig;
        float2 v0 = make_float2(o[4 * nf + 0] * inv0, o[4 * nf + 1] * inv0);
        float2 v1 = make_float2(o[4 * nf + 2] * inv1, o[4 * nf + 3] * inv1);
        *(float2*)(o0 + col) = v0;
        *(float2*)(o1 + col) = v1;
    }
}

// ---------------------------------------------------------------------------
extern "C" void kernel_launch(void* const* d_in, const int* in_sizes, int n_in,
                              void* d_out, int out_size) {
    const float* oe_raw = nullptr;
    const float* od = nullptr;
    for (int i = 0; i < n_in; ++i) {
        if (in_sizes[i] == SRC * BB * HH2) oe_raw = (const float*)d_in[i];
        else if (in_sizes[i] == TGT * BB * HH) od = (const float*)d_in[i];
    }
    float* out = (float*)d_out;

    const size_t smem_bytes =
        (size_t)(MT * HSTR * 2 + NS * HSTR * 2) * sizeof(__half)
        + (size_t)MT * PSTR * sizeof(float)
        + (size_t)MT * PSTRH * sizeof(__half)
        + 3 * MT * sizeof(float);
    cudaFuncSetAttribute(flash_kernel, cudaFuncAttributeMaxDynamicSharedMemorySize,
                         (int)smem_bytes);

    {
        const size_t total = (size_t)BB * SRC * HH / 4;
        const int threads = 256;
        const int blocks = (int)((total + threads - 1) / threads);
        prep_oe_kernel<<<blocks, threads>>>(oe_raw);
    }
    {
        dim3 grid(TGT / MT, BB);
        flash_kernel<<<grid, 256, smem_bytes>>>(od, out);
    }
}